// round 1
// baseline (speedup 1.0000x reference)
#include <cuda_runtime.h>
#include <cstdint>

// Problem constants (fixed by the dataset)
#define NE     1600000
#define D      128
#define TWO_D  256
#define SEG    50000

// Monotone-mapped init value: fmap(-inf) = ~0xFF800000 = 0x007FFFFF
#define MAX_INIT 0x007FFFFFu

// Scratch: device globals (no cudaMalloc allowed)
static __device__ float    g_sadd[(size_t)SEG * D];
static __device__ unsigned g_smax[(size_t)SEG * D];

// Monotone float<->uint mapping so unsigned atomicMax == float max
__device__ __forceinline__ unsigned fmap(float x) {
    unsigned u = __float_as_uint(x);
    return (u & 0x80000000u) ? ~u : (u | 0x80000000u);
}
__device__ __forceinline__ float funmap(unsigned u) {
    return __uint_as_float((u & 0x80000000u) ? (u ^ 0x80000000u) : ~u);
}

// ---------------------------------------------------------------------------
// Kernel 1: init accumulators (s_add = 0, s_max = map(-inf))
// ---------------------------------------------------------------------------
__global__ void __launch_bounds__(256) init_kernel() {
    size_t i = (size_t)blockIdx.x * blockDim.x + threadIdx.x;
    if (i < (size_t)SEG * D / 4) {
        ((float4*)g_sadd)[i] = make_float4(0.f, 0.f, 0.f, 0.f);
        ((uint4*)g_smax)[i]  = make_uint4(MAX_INIT, MAX_INIT, MAX_INIT, MAX_INIT);
    }
}

// ---------------------------------------------------------------------------
// Kernel 2: scatter. One warp per edge; each lane owns 4 consecutive features
// (float4). Streaming loads (__ldcs) keep the 819 MB src stream from
// thrashing L2 where the 51 MB accumulator set lives.
// ---------------------------------------------------------------------------
__global__ void __launch_bounds__(256) scatter_kernel(const float* __restrict__ src,
                                                      const int* __restrict__ index) {
    int e    = (int)((blockIdx.x * 256u + threadIdx.x) >> 5);
    int lane = threadIdx.x & 31;
    if (e >= NE) return;

    int seg = __ldg(index + e);
    float4 v = __ldcs((const float4*)(src + (size_t)e * D) + lane);

    size_t base = (size_t)seg * D + (size_t)lane * 4;

    // Vectorized fire-and-forget add: 1 RED instruction for 4 floats
    size_t ap = __cvta_generic_to_global(g_sadd + base);
    asm volatile("red.global.add.v4.f32 [%0], {%1, %2, %3, %4};"
                 :: "l"(ap), "f"(v.x), "f"(v.y), "f"(v.z), "f"(v.w)
                 : "memory");

    unsigned* mp = g_smax + base;
    atomicMax(mp + 0, fmap(v.x));
    atomicMax(mp + 1, fmap(v.y));
    atomicMax(mp + 2, fmap(v.z));
    atomicMax(mp + 3, fmap(v.w));
}

// ---------------------------------------------------------------------------
// Kernel 3: out[n, d] = sum_k cat[n, k] * W[d, k] + b[d]
// cat[n, :128] = s_add[n], cat[n, 128:] = clamp(s_max[n])
// Register-tiled fp32 GEMM with packed fma.rn.f32x2 (FFMA2).
// Block tile: 64 rows x 128 cols, BK = 32. 256 threads: tx(32) -> 4 cols,
// ty(8) -> 8 rows per thread. Accumulators packed as f32x2 over col pairs.
// ---------------------------------------------------------------------------
#define BM 64
#define BN 128
#define BK 32
#define AS_STRIDE 68    // 64 + 4 pad: keeps 16B alignment, kills STS conflicts
#define BS_STRIDE 132   // 128 + 4 pad

__global__ void __launch_bounds__(256) gemm_kernel(const float* __restrict__ W,
                                                   const float* __restrict__ bias,
                                                   float* __restrict__ out) {
    __shared__ float As[BK * AS_STRIDE];  // As[k][m] : cat tile, k-major
    __shared__ float Bs[BK * BS_STRIDE];  // Bs[k][d] : W transposed tile

    int tid = threadIdx.x;
    int tx = tid & 31;   // col group: cols tx*4 .. tx*4+3
    int ty = tid >> 5;   // row group: rows ty*8 .. ty*8+7
    int row0 = blockIdx.x * BM;

    unsigned long long acc2[8][2];  // [row][col-pair] packed f32x2
    #pragma unroll
    for (int i = 0; i < 8; i++) { acc2[i][0] = 0ull; acc2[i][1] = 0ull; }

    for (int kc = 0; kc < TWO_D; kc += BK) {
        // --- load A tile: 64 rows x 32 k = 512 float4, 2 per thread ---
        #pragma unroll
        for (int l = 0; l < 2; l++) {
            int idx = tid + l * 256;
            int m   = idx >> 3;
            int k4  = (idx & 7) * 4;
            int gr  = row0 + m;
            float4 v = make_float4(0.f, 0.f, 0.f, 0.f);
            if (gr < SEG) {
                int k = kc + k4;
                if (k < D) {
                    v = *(const float4*)(g_sadd + (size_t)gr * D + k);
                } else {
                    uint4 u = *(const uint4*)(g_smax + (size_t)gr * D + (k - D));
                    v.x = (u.x == MAX_INIT) ? 0.f : funmap(u.x);
                    v.y = (u.y == MAX_INIT) ? 0.f : funmap(u.y);
                    v.z = (u.z == MAX_INIT) ? 0.f : funmap(u.z);
                    v.w = (u.w == MAX_INIT) ? 0.f : funmap(u.w);
                }
            }
            As[(k4 + 0) * AS_STRIDE + m] = v.x;
            As[(k4 + 1) * AS_STRIDE + m] = v.y;
            As[(k4 + 2) * AS_STRIDE + m] = v.z;
            As[(k4 + 3) * AS_STRIDE + m] = v.w;
        }
        // --- load B tile: Bs[k][d] = W[d][kc+k]; 1024 float4, 4 per thread ---
        #pragma unroll
        for (int l = 0; l < 4; l++) {
            int idx = tid + l * 256;
            int d   = idx >> 3;
            int k4  = (idx & 7) * 4;
            float4 v = *(const float4*)(W + (size_t)d * TWO_D + kc + k4);
            Bs[(k4 + 0) * BS_STRIDE + d] = v.x;
            Bs[(k4 + 1) * BS_STRIDE + d] = v.y;
            Bs[(k4 + 2) * BS_STRIDE + d] = v.z;
            Bs[(k4 + 3) * BS_STRIDE + d] = v.w;
        }
        __syncthreads();

        #pragma unroll
        for (int kk = 0; kk < BK; kk++) {
            // broadcast row values (all lanes in a warp share ty)
            float4 a03 = *(const float4*)(As + kk * AS_STRIDE + ty * 8);
            float4 a47 = *(const float4*)(As + kk * AS_STRIDE + ty * 8 + 4);
            // col-pair values, directly as 64-bit packed f32x2
            unsigned long long b0 = *(const unsigned long long*)(Bs + kk * BS_STRIDE + tx * 4);
            unsigned long long b1 = *(const unsigned long long*)(Bs + kk * BS_STRIDE + tx * 4 + 2);
            float av[8] = {a03.x, a03.y, a03.z, a03.w, a47.x, a47.y, a47.z, a47.w};
            #pragma unroll
            for (int i = 0; i < 8; i++) {
                unsigned long long asplat;
                asm("mov.b64 %0, {%1, %1};" : "=l"(asplat) : "f"(av[i]));
                asm("fma.rn.f32x2 %0, %1, %2, %0;" : "+l"(acc2[i][0]) : "l"(asplat), "l"(b0));
                asm("fma.rn.f32x2 %0, %1, %2, %0;" : "+l"(acc2[i][1]) : "l"(asplat), "l"(b1));
            }
        }
        __syncthreads();
    }

    float4 bb = *(const float4*)(bias + tx * 4);
    #pragma unroll
    for (int i = 0; i < 8; i++) {
        int gr = row0 + ty * 8 + i;
        if (gr < SEG) {
            float x0, x1, x2, x3;
            asm("mov.b64 {%0, %1}, %2;" : "=f"(x0), "=f"(x1) : "l"(acc2[i][0]));
            asm("mov.b64 {%0, %1}, %2;" : "=f"(x2), "=f"(x3) : "l"(acc2[i][1]));
            float4 o = make_float4(x0 + bb.x, x1 + bb.y, x2 + bb.z, x3 + bb.w);
            *(float4*)(out + (size_t)gr * D + tx * 4) = o;
        }
    }
}

// ---------------------------------------------------------------------------
// Launch: init -> scatter -> gemm (stream-ordered, graph-capturable)
// Inputs (metadata order): src[f32 NE*D], index[i32 NE], W[f32 D*2D], b[f32 D]
// ---------------------------------------------------------------------------
extern "C" void kernel_launch(void* const* d_in, const int* in_sizes, int n_in,
                              void* d_out, int out_size) {
    const float* src   = (const float*)d_in[0];
    const int*   index = (const int*)d_in[1];
    const float* W     = (const float*)d_in[2];
    const float* bias  = (const float*)d_in[3];
    float* out = (float*)d_out;

    (void)in_sizes; (void)n_in; (void)out_size;

    // init: SEG*D/4 = 1,600,000 float4 slots
    init_kernel<<<(SEG * D / 4 + 255) / 256, 256>>>();

    // scatter: 1 warp per edge, 8 warps per block
    scatter_kernel<<<NE / 8, 256>>>(src, index);

    // gemm: 64 rows per block
    gemm_kernel<<<(SEG + BM - 1) / BM, 256>>>(W, bias, out);
}

// round 2
// speedup vs baseline: 1.9017x; 1.9017x over previous
#include <cuda_runtime.h>
#include <cstdint>

// Problem constants (fixed by the dataset)
#define NE     1600000
#define D      128
#define TWO_D  256
#define SEG    50000

// Scratch: device globals (no cudaMalloc allowed)
static __device__ float g_sadd[(size_t)SEG * D];   // segment sums
static __device__ float g_smax[(size_t)SEG * D];   // segment maxes (empty -> 0)
static __device__ int   g_cnt[SEG];                // histogram
static __device__ int   g_offs[SEG + 1];           // exclusive offsets
static __device__ int   g_cur[SEG];                // rank cursors
static __device__ int   g_perm[NE];                // edge ids grouped by segment

// ---------------------------------------------------------------------------
// Kernel 1: zero the histogram counters
// ---------------------------------------------------------------------------
__global__ void __launch_bounds__(256) zero_cnt_kernel() {
    int i = blockIdx.x * 256 + threadIdx.x;
    if (i < SEG) g_cnt[i] = 0;
}

// ---------------------------------------------------------------------------
// Kernel 2: histogram of index. int4 loads, fire-and-forget adds.
// ---------------------------------------------------------------------------
__global__ void __launch_bounds__(256) hist_kernel(const int* __restrict__ index) {
    int i = blockIdx.x * 256 + threadIdx.x;      // one int4 (4 edges) per thread
    if (i < NE / 4) {
        int4 s = ((const int4*)index)[i];
        atomicAdd(&g_cnt[s.x], 1);
        atomicAdd(&g_cnt[s.y], 1);
        atomicAdd(&g_cnt[s.z], 1);
        atomicAdd(&g_cnt[s.w], 1);
    }
}

// ---------------------------------------------------------------------------
// Kernel 3: exclusive scan of the 50K histogram. One block, 1024 threads,
// 49 counters per thread + Hillis-Steele scan over the 1024 partials.
// ---------------------------------------------------------------------------
__global__ void __launch_bounds__(1024) scan_kernel() {
    __shared__ int part[1024];
    const int CH = 49;                            // 1024*49 = 50176 >= 50000
    int t  = threadIdx.x;
    int lo = t * CH;
    int hi = lo + CH; if (hi > SEG) hi = SEG;
    if (lo > SEG) lo = SEG;

    int s = 0;
    for (int i = lo; i < hi; i++) s += g_cnt[i];
    part[t] = s;
    __syncthreads();

    // inclusive scan over part[]
    for (int off = 1; off < 1024; off <<= 1) {
        int v = 0;
        if (t >= off) v = part[t - off];
        __syncthreads();
        if (t >= off) part[t] += v;
        __syncthreads();
    }

    int run = (t == 0) ? 0 : part[t - 1];         // exclusive prefix of this chunk
    for (int i = lo; i < hi; i++) {
        g_offs[i] = run;
        g_cur[i]  = run;
        run += g_cnt[i];
    }
    if (t == 1023) g_offs[SEG] = part[1023];      // total == NE
}

// ---------------------------------------------------------------------------
// Kernel 4: build permutation (edges grouped by segment)
// ---------------------------------------------------------------------------
__global__ void __launch_bounds__(256) rank_kernel(const int* __restrict__ index) {
    int e = blockIdx.x * 256 + threadIdx.x;
    if (e < NE) {
        int seg = index[e];
        int pos = atomicAdd(&g_cur[seg], 1);
        g_perm[pos] = e;
    }
}

// ---------------------------------------------------------------------------
// Kernel 5: segment reduce. One warp per segment; lane owns 4 features.
// Pure streaming loads, register accumulation, single store. No atomics.
// Unrolled x2 for memory-level parallelism.
// ---------------------------------------------------------------------------
__global__ void __launch_bounds__(256) reduce_kernel(const float* __restrict__ src) {
    int seg  = blockIdx.x * 8 + (threadIdx.x >> 5);
    int lane = threadIdx.x & 31;
    if (seg >= SEG) return;

    int start = g_offs[seg];
    int end   = g_offs[seg + 1];

    float4 sum = make_float4(0.f, 0.f, 0.f, 0.f);
    float4 mx  = make_float4(-__builtin_huge_valf(), -__builtin_huge_valf(),
                             -__builtin_huge_valf(), -__builtin_huge_valf());

    int i = start;
    for (; i + 1 < end; i += 2) {
        int e0 = g_perm[i];
        int e1 = g_perm[i + 1];
        float4 v0 = __ldcs((const float4*)(src + (size_t)e0 * D) + lane);
        float4 v1 = __ldcs((const float4*)(src + (size_t)e1 * D) + lane);
        sum.x += v0.x; sum.y += v0.y; sum.z += v0.z; sum.w += v0.w;
        mx.x = fmaxf(mx.x, v0.x); mx.y = fmaxf(mx.y, v0.y);
        mx.z = fmaxf(mx.z, v0.z); mx.w = fmaxf(mx.w, v0.w);
        sum.x += v1.x; sum.y += v1.y; sum.z += v1.z; sum.w += v1.w;
        mx.x = fmaxf(mx.x, v1.x); mx.y = fmaxf(mx.y, v1.y);
        mx.z = fmaxf(mx.z, v1.z); mx.w = fmaxf(mx.w, v1.w);
    }
    if (i < end) {
        int e0 = g_perm[i];
        float4 v0 = __ldcs((const float4*)(src + (size_t)e0 * D) + lane);
        sum.x += v0.x; sum.y += v0.y; sum.z += v0.z; sum.w += v0.w;
        mx.x = fmaxf(mx.x, v0.x); mx.y = fmaxf(mx.y, v0.y);
        mx.z = fmaxf(mx.z, v0.z); mx.w = fmaxf(mx.w, v0.w);
    }

    if (start == end) mx = make_float4(0.f, 0.f, 0.f, 0.f);  // torch_scatter: empty max = 0

    size_t base = (size_t)seg * D + (size_t)lane * 4;
    *(float4*)(g_sadd + base) = sum;
    *(float4*)(g_smax + base) = mx;
}

// ---------------------------------------------------------------------------
// Kernel 6: out[n, d] = sum_k cat[n, k] * W[d, k] + b[d]
// cat[n, :128] = s_add[n], cat[n, 128:] = s_max[n]
// Register-tiled fp32 GEMM with packed fma.rn.f32x2 (FFMA2).
// ---------------------------------------------------------------------------
#define BM 64
#define BN 128
#define BK 32
#define AS_STRIDE 68    // 64 + 4 pad
#define BS_STRIDE 132   // 128 + 4 pad

__global__ void __launch_bounds__(256) gemm_kernel(const float* __restrict__ W,
                                                   const float* __restrict__ bias,
                                                   float* __restrict__ out) {
    __shared__ float As[BK * AS_STRIDE];  // As[k][m]
    __shared__ float Bs[BK * BS_STRIDE];  // Bs[k][d]

    int tid = threadIdx.x;
    int tx = tid & 31;   // cols tx*4 .. tx*4+3
    int ty = tid >> 5;   // rows ty*8 .. ty*8+7
    int row0 = blockIdx.x * BM;

    unsigned long long acc2[8][2];
    #pragma unroll
    for (int i = 0; i < 8; i++) { acc2[i][0] = 0ull; acc2[i][1] = 0ull; }

    for (int kc = 0; kc < TWO_D; kc += BK) {
        #pragma unroll
        for (int l = 0; l < 2; l++) {
            int idx = tid + l * 256;
            int m   = idx >> 3;
            int k4  = (idx & 7) * 4;
            int gr  = row0 + m;
            float4 v = make_float4(0.f, 0.f, 0.f, 0.f);
            if (gr < SEG) {
                int k = kc + k4;
                if (k < D) v = *(const float4*)(g_sadd + (size_t)gr * D + k);
                else       v = *(const float4*)(g_smax + (size_t)gr * D + (k - D));
            }
            As[(k4 + 0) * AS_STRIDE + m] = v.x;
            As[(k4 + 1) * AS_STRIDE + m] = v.y;
            As[(k4 + 2) * AS_STRIDE + m] = v.z;
            As[(k4 + 3) * AS_STRIDE + m] = v.w;
        }
        #pragma unroll
        for (int l = 0; l < 4; l++) {
            int idx = tid + l * 256;
            int d   = idx >> 3;
            int k4  = (idx & 7) * 4;
            float4 v = *(const float4*)(W + (size_t)d * TWO_D + kc + k4);
            Bs[(k4 + 0) * BS_STRIDE + d] = v.x;
            Bs[(k4 + 1) * BS_STRIDE + d] = v.y;
            Bs[(k4 + 2) * BS_STRIDE + d] = v.z;
            Bs[(k4 + 3) * BS_STRIDE + d] = v.w;
        }
        __syncthreads();

        #pragma unroll
        for (int kk = 0; kk < BK; kk++) {
            float4 a03 = *(const float4*)(As + kk * AS_STRIDE + ty * 8);
            float4 a47 = *(const float4*)(As + kk * AS_STRIDE + ty * 8 + 4);
            unsigned long long b0 = *(const unsigned long long*)(Bs + kk * BS_STRIDE + tx * 4);
            unsigned long long b1 = *(const unsigned long long*)(Bs + kk * BS_STRIDE + tx * 4 + 2);
            float av[8] = {a03.x, a03.y, a03.z, a03.w, a47.x, a47.y, a47.z, a47.w};
            #pragma unroll
            for (int i = 0; i < 8; i++) {
                unsigned long long asplat;
                asm("mov.b64 %0, {%1, %1};" : "=l"(asplat) : "f"(av[i]));
                asm("fma.rn.f32x2 %0, %1, %2, %0;" : "+l"(acc2[i][0]) : "l"(asplat), "l"(b0));
                asm("fma.rn.f32x2 %0, %1, %2, %0;" : "+l"(acc2[i][1]) : "l"(asplat), "l"(b1));
            }
        }
        __syncthreads();
    }

    float4 bb = *(const float4*)(bias + tx * 4);
    #pragma unroll
    for (int i = 0; i < 8; i++) {
        int gr = row0 + ty * 8 + i;
        if (gr < SEG) {
            float x0, x1, x2, x3;
            asm("mov.b64 {%0, %1}, %2;" : "=f"(x0), "=f"(x1) : "l"(acc2[i][0]));
            asm("mov.b64 {%0, %1}, %2;" : "=f"(x2), "=f"(x3) : "l"(acc2[i][1]));
            float4 o = make_float4(x0 + bb.x, x1 + bb.y, x2 + bb.z, x3 + bb.w);
            *(float4*)(out + (size_t)gr * D + tx * 4) = o;
        }
    }
}

// ---------------------------------------------------------------------------
// Launch pipeline: zero -> hist -> scan -> rank -> reduce -> gemm
// Inputs (metadata order): src[f32 NE*D], index[i32 NE], W[f32 D*2D], b[f32 D]
// ---------------------------------------------------------------------------
extern "C" void kernel_launch(void* const* d_in, const int* in_sizes, int n_in,
                              void* d_out, int out_size) {
    const float* src   = (const float*)d_in[0];
    const int*   index = (const int*)d_in[1];
    const float* W     = (const float*)d_in[2];
    const float* bias  = (const float*)d_in[3];
    float* out = (float*)d_out;

    (void)in_sizes; (void)n_in; (void)out_size;

    zero_cnt_kernel<<<(SEG + 255) / 256, 256>>>();
    hist_kernel<<<(NE / 4 + 255) / 256, 256>>>(index);
    scan_kernel<<<1, 1024>>>();
    rank_kernel<<<(NE + 255) / 256, 256>>>(index);
    reduce_kernel<<<SEG / 8, 256>>>(src);
    gemm_kernel<<<(SEG + BM - 1) / BM, 256>>>(W, bias, out);
}